// round 2
// baseline (speedup 1.0000x reference)
#include <cuda_runtime.h>
#include <math.h>

#define BATCH 512
#define NUNITS 256
#define IMGD 64
#define PATCHD 9216      // 32*32*9
#define ENCK 9984        // 9216 + 256 + 256 (enc_kernel rows) + 256 (enc_rec rows)
#define GATES 1024
#define DECK 512

// ---- scratch partition (floats) ----
#define OFF_WENC   0u
#define SZ_WENC    (ENCK * GATES)                 // 10,223,616
#define OFF_WDEC   (OFF_WENC + SZ_WENC)
#define SZ_WDEC    (DECK * GATES)                 // 524,288
#define OFF_ENCIN  (OFF_WDEC + SZ_WDEC)
#define SZ_ENCIN   (BATCH * ENCK)                 // 5,111,808
#define OFF_DECIN  (OFF_ENCIN + SZ_ENCIN)
#define SZ_DECIN   (BATCH * DECK)                 // 262,144
#define OFF_XHAT   (OFF_DECIN + SZ_DECIN)
#define SZ_XHAT    (BATCH * IMGD * IMGD)          // 2,097,152
#define OFF_ZENC   (OFF_XHAT + SZ_XHAT)
#define SZ_Z       (BATCH * GATES)                // 524,288
#define OFF_ZDEC   (OFF_ZENC + SZ_Z)
#define OFF_HENC   (OFF_ZDEC + SZ_Z)
#define SZ_STATE   (BATCH * NUNITS)               // 131,072
#define OFF_CENC   (OFF_HENC + SZ_STATE)
#define OFF_HDEC   (OFF_CENC + SZ_STATE)
#define OFF_CDEC   (OFF_HDEC + SZ_STATE)
#define SCRATCH_TOTAL (OFF_CDEC + SZ_STATE)       // 19,791,872 floats ~79.2 MB

__device__ float g_scratch[SCRATCH_TOTAL];

__device__ __forceinline__ float sigmoidf_(float x) { return 1.f / (1.f + expf(-x)); }

// ------------------------------------------------------------------
// setup: assemble combined weight matrices, zero states + canvas
// ------------------------------------------------------------------
__global__ void setup_kernel(const float* __restrict__ enc_k, const float* __restrict__ enc_r,
                             const float* __restrict__ dec_k, const float* __restrict__ dec_r,
                             float* __restrict__ Wenc, float* __restrict__ Wdec,
                             float* __restrict__ henc, float* __restrict__ cenc,
                             float* __restrict__ hdec, float* __restrict__ cdec,
                             float* __restrict__ canvas)
{
    const int NENC_K = 9728 * GATES;          // rows from enc_kernel
    const int NTOT   = ENCK * GATES;
    for (int i = blockIdx.x * blockDim.x + threadIdx.x; i < NTOT;
         i += gridDim.x * blockDim.x) {
        Wenc[i] = (i < NENC_K) ? enc_k[i] : enc_r[i - NENC_K];
        if (i < 256 * GATES)          Wdec[i] = dec_k[i];
        else if (i < 512 * GATES)     Wdec[i] = dec_r[i - 256 * GATES];
        if (i < BATCH * IMGD * IMGD)  canvas[i] = 0.f;
        if (i < BATCH * NUNITS) { henc[i] = 0.f; cenc[i] = 0.f; hdec[i] = 0.f; cdec[i] = 0.f; }
    }
}

// ------------------------------------------------------------------
// x_hat = x - sigmoid(canvas)
// ------------------------------------------------------------------
__global__ void xhat_kernel(const float* __restrict__ x, const float* __restrict__ canvas,
                            float* __restrict__ xhat)
{
    int i = blockIdx.x * blockDim.x + threadIdx.x;
    if (i < BATCH * IMGD * IMGD) xhat[i] = x[i] - sigmoidf_(canvas[i]);
}

// ------------------------------------------------------------------
// build enc_in row: [patches(9216) | h_dec | h_dec | h_enc]
// grid: (9984/256, BATCH)
// ------------------------------------------------------------------
__global__ void gather_kernel(const float* __restrict__ xhat, const float* __restrict__ hdec,
                              const float* __restrict__ henc, float* __restrict__ encin)
{
    int k = blockIdx.x * blockDim.x + threadIdx.x;   // 0..9983
    int b = blockIdx.y;
    float v;
    if (k < PATCHD) {
        int ip  = k / 288;           // 32*9
        int rem = k - ip * 288;
        int jp  = rem / 9;
        int t   = rem - jp * 9;
        int r = 2 * ip + t / 3;
        int c = 2 * jp + t % 3;
        v = (r < IMGD && c < IMGD) ? xhat[b * (IMGD * IMGD) + r * IMGD + c] : 0.f;
    } else if (k < PATCHD + NUNITS) {
        v = hdec[b * NUNITS + (k - PATCHD)];
    } else if (k < PATCHD + 2 * NUNITS) {
        v = hdec[b * NUNITS + (k - PATCHD - NUNITS)];
    } else {
        v = henc[b * NUNITS + (k - PATCHD - 2 * NUNITS)];
    }
    encin[(size_t)b * ENCK + k] = v;
}

// ------------------------------------------------------------------
// SGEMM: C[M,N] (+)= A[M,K] @ B[K,N] (+ bias)
// 64x64 tile, BK=16, 256 threads, 4x4 per thread, register prefetch.
// Requires M%64==0, N%64==0, K%16==0.
// ------------------------------------------------------------------
template<bool ACCUM, bool BIAS>
__global__ void sgemm64(const float* __restrict__ A, const float* __restrict__ Bm,
                        const float* __restrict__ bias, float* __restrict__ C,
                        int M, int N, int K)
{
    __shared__ float As[16][64];
    __shared__ float Bs[16][64];
    const int tid = threadIdx.x;
    const int tx = tid & 15, ty = tid >> 4;
    const int bm = blockIdx.y * 64, bn = blockIdx.x * 64;
    const int arow = tid >> 2, acol = (tid & 3) << 2;
    const int brow = tid >> 4, bcol = (tid & 15) << 2;

    const float* Ap = A + (size_t)(bm + arow) * K + acol;
    const float* Bp = Bm + (size_t)brow * N + bn + bcol;

    float4 av = *(const float4*)Ap;
    float4 bv = *(const float4*)Bp;
    float acc[4][4] = {};

    for (int k0 = 16; k0 <= K; k0 += 16) {
        As[acol + 0][arow] = av.x;
        As[acol + 1][arow] = av.y;
        As[acol + 2][arow] = av.z;
        As[acol + 3][arow] = av.w;
        *(float4*)&Bs[brow][bcol] = bv;
        __syncthreads();
        if (k0 < K) {
            av = *(const float4*)(Ap + k0);
            bv = *(const float4*)(Bp + (size_t)k0 * N);
        }
#pragma unroll
        for (int kk = 0; kk < 16; kk++) {
            float4 a = *(const float4*)&As[kk][ty << 2];
            float4 b = *(const float4*)&Bs[kk][tx << 2];
            acc[0][0] = fmaf(a.x, b.x, acc[0][0]);
            acc[0][1] = fmaf(a.x, b.y, acc[0][1]);
            acc[0][2] = fmaf(a.x, b.z, acc[0][2]);
            acc[0][3] = fmaf(a.x, b.w, acc[0][3]);
            acc[1][0] = fmaf(a.y, b.x, acc[1][0]);
            acc[1][1] = fmaf(a.y, b.y, acc[1][1]);
            acc[1][2] = fmaf(a.y, b.z, acc[1][2]);
            acc[1][3] = fmaf(a.y, b.w, acc[1][3]);
            acc[2][0] = fmaf(a.z, b.x, acc[2][0]);
            acc[2][1] = fmaf(a.z, b.y, acc[2][1]);
            acc[2][2] = fmaf(a.z, b.z, acc[2][2]);
            acc[2][3] = fmaf(a.z, b.w, acc[2][3]);
            acc[3][0] = fmaf(a.w, b.x, acc[3][0]);
            acc[3][1] = fmaf(a.w, b.y, acc[3][1]);
            acc[3][2] = fmaf(a.w, b.z, acc[3][2]);
            acc[3][3] = fmaf(a.w, b.w, acc[3][3]);
        }
        __syncthreads();
    }

#pragma unroll
    for (int i = 0; i < 4; i++) {
        size_t off = (size_t)(bm + (ty << 2) + i) * N + bn + (tx << 2);
        float4 r;
        r.x = acc[i][0]; r.y = acc[i][1]; r.z = acc[i][2]; r.w = acc[i][3];
        if (BIAS) {
            const float* bb = bias + bn + (tx << 2);
            r.x += bb[0]; r.y += bb[1]; r.z += bb[2]; r.w += bb[3];
        }
        if (ACCUM) {
            float4 old = *(const float4*)(C + off);
            r.x += old.x; r.y += old.y; r.z += old.z; r.w += old.w;
        }
        *(float4*)(C + off) = r;
    }
}

// ------------------------------------------------------------------
// LSTM cell elementwise (Keras gate order i,f,g,o), bias folded here
// ------------------------------------------------------------------
__global__ void lstm_kernel(const float* __restrict__ z, const float* __restrict__ bias,
                            float* __restrict__ h, float* __restrict__ c)
{
    int idx = blockIdx.x * blockDim.x + threadIdx.x;
    if (idx >= BATCH * NUNITS) return;
    int b = idx >> 8, u = idx & 255;
    const float* zr = z + (size_t)b * GATES;
    float zi = zr[u]             + bias[u];
    float zf = zr[256 + u]       + bias[256 + u];
    float zg = zr[512 + u]       + bias[512 + u];
    float zo = zr[768 + u]       + bias[768 + u];
    float cn = sigmoidf_(zf) * c[idx] + sigmoidf_(zi) * tanhf(zg);
    float hn = sigmoidf_(zo) * tanhf(cn);
    c[idx] = cn;
    h[idx] = hn;
}

// ------------------------------------------------------------------
// attention: logits = h_enc @ W_enc + b_enc ; softmax ; z = attn @ W_enc^T
// also assembles dec input row [z | h_dec].  One block per batch row.
// ------------------------------------------------------------------
__global__ void attn_kernel(const float* __restrict__ Wenc, const float* __restrict__ benc,
                            const float* __restrict__ henc, const float* __restrict__ hdec,
                            float* __restrict__ decin)
{
    int b = blockIdx.x;
    int t = threadIdx.x;   // 0..255
    __shared__ float red[10][8];
    __shared__ float lg[10];

    float h = henc[b * NUNITS + t];
    float w[10];
#pragma unroll
    for (int s = 0; s < 10; s++) w[s] = Wenc[t * 10 + s];

    int lane = t & 31, warp = t >> 5;
#pragma unroll
    for (int s = 0; s < 10; s++) {
        float v = h * w[s];
        v += __shfl_down_sync(0xffffffffu, v, 16);
        v += __shfl_down_sync(0xffffffffu, v, 8);
        v += __shfl_down_sync(0xffffffffu, v, 4);
        v += __shfl_down_sync(0xffffffffu, v, 2);
        v += __shfl_down_sync(0xffffffffu, v, 1);
        if (lane == 0) red[s][warp] = v;
    }
    __syncthreads();
    if (t < 10) {
        float v = 0.f;
#pragma unroll
        for (int wg = 0; wg < 8; wg++) v += red[t][wg];
        lg[t] = v + benc[t];
    }
    __syncthreads();

    // each thread computes softmax locally over the 10 shared logits
    float mx = lg[0];
#pragma unroll
    for (int s = 1; s < 10; s++) mx = fmaxf(mx, lg[s]);
    float e[10], sum = 0.f;
#pragma unroll
    for (int s = 0; s < 10; s++) { e[s] = expf(lg[s] - mx); sum += e[s]; }
    float inv = 1.f / sum;
    float zv = 0.f;
#pragma unroll
    for (int s = 0; s < 10; s++) zv = fmaf(e[s] * inv, w[s], zv);

    decin[(size_t)b * DECK + t] = zv;
    decin[(size_t)b * DECK + NUNITS + t] = hdec[b * NUNITS + t];
}

// ------------------------------------------------------------------
extern "C" void kernel_launch(void* const* d_in, const int* in_sizes, int n_in,
                              void* d_out, int out_size)
{
    const float* x          = (const float*)d_in[0];
    const float* enc_kernel = (const float*)d_in[1];
    const float* enc_rec    = (const float*)d_in[2];
    const float* enc_bias   = (const float*)d_in[3];
    const float* dec_kernel = (const float*)d_in[4];
    const float* dec_rec    = (const float*)d_in[5];
    const float* dec_bias   = (const float*)d_in[6];
    const float* W_enc      = (const float*)d_in[7];
    const float* b_enc      = (const float*)d_in[8];
    const float* W_dec      = (const float*)d_in[9];
    const float* b_dec      = (const float*)d_in[10];
    float* canvas = (float*)d_out;

    float* base = nullptr;
    cudaGetSymbolAddress((void**)&base, g_scratch);
    float* Wenc  = base + OFF_WENC;
    float* Wdec  = base + OFF_WDEC;
    float* encin = base + OFF_ENCIN;
    float* decin = base + OFF_DECIN;
    float* xhat  = base + OFF_XHAT;
    float* zenc  = base + OFF_ZENC;
    float* zdec  = base + OFF_ZDEC;
    float* henc  = base + OFF_HENC;
    float* cenc  = base + OFF_CENC;
    float* hdec  = base + OFF_HDEC;
    float* cdec  = base + OFF_CDEC;

    setup_kernel<<<(ENCK * GATES + 255) / 256, 256>>>(
        enc_kernel, enc_rec, dec_kernel, dec_rec,
        Wenc, Wdec, henc, cenc, hdec, cdec, canvas);

    for (int step = 0; step < 10; ++step) {
        xhat_kernel<<<(BATCH * IMGD * IMGD + 255) / 256, 256>>>(x, canvas, xhat);
        gather_kernel<<<dim3(ENCK / 256, BATCH), 256>>>(xhat, hdec, henc, encin);
        sgemm64<false, false><<<dim3(GATES / 64, BATCH / 64), 256>>>(
            encin, Wenc, nullptr, zenc, BATCH, GATES, ENCK);
        lstm_kernel<<<(BATCH * NUNITS + 255) / 256, 256>>>(zenc, enc_bias, henc, cenc);
        attn_kernel<<<BATCH, 256>>>(W_enc, b_enc, henc, hdec, decin);
        sgemm64<false, false><<<dim3(GATES / 64, BATCH / 64), 256>>>(
            decin, Wdec, nullptr, zdec, BATCH, GATES, DECK);
        lstm_kernel<<<(BATCH * NUNITS + 255) / 256, 256>>>(zdec, dec_bias, hdec, cdec);
        sgemm64<true, true><<<dim3(IMGD * IMGD / 64, BATCH / 64), 256>>>(
            hdec, W_dec, b_dec, canvas, BATCH, IMGD * IMGD, NUNITS);
    }
}

// round 3
// speedup vs baseline: 1.0007x; 1.0007x over previous
#include <cuda_runtime.h>
#include <math.h>

#define BATCH 512
#define NUNITS 256
#define IMGD 64
#define PATCHD 9216      // 32*32*9
#define ENCK 9984        // 9216 + 256 + 256 (enc_kernel rows) + 256 (enc_rec rows)
#define GATES 1024
#define DECK 512

// ---- scratch partition (floats) ----
#define OFF_WENC   0u
#define SZ_WENC    (ENCK * GATES)                 // 10,223,616
#define OFF_WDEC   (OFF_WENC + SZ_WENC)
#define SZ_WDEC    (DECK * GATES)                 // 524,288
#define OFF_ENCIN  (OFF_WDEC + SZ_WDEC)
#define SZ_ENCIN   (BATCH * ENCK)                 // 5,111,808
#define OFF_DECIN  (OFF_ENCIN + SZ_ENCIN)
#define SZ_DECIN   (BATCH * DECK)                 // 262,144
#define OFF_XHAT   (OFF_DECIN + SZ_DECIN)
#define SZ_XHAT    (BATCH * IMGD * IMGD)          // 2,097,152
#define OFF_ZENC   (OFF_XHAT + SZ_XHAT)
#define SZ_Z       (BATCH * GATES)                // 524,288
#define OFF_ZDEC   (OFF_ZENC + SZ_Z)
#define OFF_HENC   (OFF_ZDEC + SZ_Z)
#define SZ_STATE   (BATCH * NUNITS)               // 131,072
#define OFF_CENC   (OFF_HENC + SZ_STATE)
#define OFF_HDEC   (OFF_CENC + SZ_STATE)
#define OFF_CDEC   (OFF_HDEC + SZ_STATE)
#define SCRATCH_TOTAL (OFF_CDEC + SZ_STATE)       // 19,791,872 floats ~79.2 MB

__device__ float g_scratch[SCRATCH_TOTAL];

__device__ __forceinline__ float sigmoidf_(float x) { return 1.f / (1.f + expf(-x)); }

// ------------------------------------------------------------------
// setup: assemble combined weight matrices, zero states + canvas
// ------------------------------------------------------------------
__global__ void setup_kernel(const float* __restrict__ enc_k, const float* __restrict__ enc_r,
                             const float* __restrict__ dec_k, const float* __restrict__ dec_r,
                             float* __restrict__ Wenc, float* __restrict__ Wdec,
                             float* __restrict__ henc, float* __restrict__ cenc,
                             float* __restrict__ hdec, float* __restrict__ cdec,
                             float* __restrict__ canvas)
{
    const int NENC_K = 9728 * GATES;          // rows from enc_kernel
    const int NTOT   = ENCK * GATES;
    for (int i = blockIdx.x * blockDim.x + threadIdx.x; i < NTOT;
         i += gridDim.x * blockDim.x) {
        Wenc[i] = (i < NENC_K) ? enc_k[i] : enc_r[i - NENC_K];
        if (i < 256 * GATES)          Wdec[i] = dec_k[i];
        else if (i < 512 * GATES)     Wdec[i] = dec_r[i - 256 * GATES];
        if (i < BATCH * IMGD * IMGD)  canvas[i] = 0.f;
        if (i < BATCH * NUNITS) { henc[i] = 0.f; cenc[i] = 0.f; hdec[i] = 0.f; cdec[i] = 0.f; }
    }
}

// ------------------------------------------------------------------
// x_hat = x - sigmoid(canvas)
// ------------------------------------------------------------------
__global__ void xhat_kernel(const float* __restrict__ x, const float* __restrict__ canvas,
                            float* __restrict__ xhat)
{
    int i = blockIdx.x * blockDim.x + threadIdx.x;
    if (i < BATCH * IMGD * IMGD) xhat[i] = x[i] - sigmoidf_(canvas[i]);
}

// ------------------------------------------------------------------
// build enc_in row: [patches(9216) | h_dec | h_dec | h_enc]
// grid: (9984/256, BATCH)
// ------------------------------------------------------------------
__global__ void gather_kernel(const float* __restrict__ xhat, const float* __restrict__ hdec,
                              const float* __restrict__ henc, float* __restrict__ encin)
{
    int k = blockIdx.x * blockDim.x + threadIdx.x;   // 0..9983
    int b = blockIdx.y;
    float v;
    if (k < PATCHD) {
        int ip  = k / 288;           // 32*9
        int rem = k - ip * 288;
        int jp  = rem / 9;
        int t   = rem - jp * 9;
        int r = 2 * ip + t / 3;
        int c = 2 * jp + t % 3;
        v = (r < IMGD && c < IMGD) ? xhat[b * (IMGD * IMGD) + r * IMGD + c] : 0.f;
    } else if (k < PATCHD + NUNITS) {
        v = hdec[b * NUNITS + (k - PATCHD)];
    } else if (k < PATCHD + 2 * NUNITS) {
        v = hdec[b * NUNITS + (k - PATCHD - NUNITS)];
    } else {
        v = henc[b * NUNITS + (k - PATCHD - 2 * NUNITS)];
    }
    encin[(size_t)b * ENCK + k] = v;
}

// ------------------------------------------------------------------
// SGEMM: C[M,N] (+)= A[M,K] @ B[K,N] (+ bias)
// 64x64 tile, BK=16, 256 threads, 4x4 per thread, register prefetch.
// Requires M%64==0, N%64==0, K%16==0.
// ------------------------------------------------------------------
template<bool ACCUM, bool BIAS>
__global__ void sgemm64(const float* __restrict__ A, const float* __restrict__ Bm,
                        const float* __restrict__ bias, float* __restrict__ C,
                        int M, int N, int K)
{
    __shared__ float As[16][64];
    __shared__ float Bs[16][64];
    const int tid = threadIdx.x;
    const int tx = tid & 15, ty = tid >> 4;
    const int bm = blockIdx.y * 64, bn = blockIdx.x * 64;
    const int arow = tid >> 2, acol = (tid & 3) << 2;
    const int brow = tid >> 4, bcol = (tid & 15) << 2;

    const float* Ap = A + (size_t)(bm + arow) * K + acol;
    const float* Bp = Bm + (size_t)brow * N + bn + bcol;

    float4 av = *(const float4*)Ap;
    float4 bv = *(const float4*)Bp;
    float acc[4][4] = {};

    for (int k0 = 16; k0 <= K; k0 += 16) {
        As[acol + 0][arow] = av.x;
        As[acol + 1][arow] = av.y;
        As[acol + 2][arow] = av.z;
        As[acol + 3][arow] = av.w;
        *(float4*)&Bs[brow][bcol] = bv;
        __syncthreads();
        if (k0 < K) {
            av = *(const float4*)(Ap + k0);
            bv = *(const float4*)(Bp + (size_t)k0 * N);
        }
#pragma unroll
        for (int kk = 0; kk < 16; kk++) {
            float4 a = *(const float4*)&As[kk][ty << 2];
            float4 b = *(const float4*)&Bs[kk][tx << 2];
            acc[0][0] = fmaf(a.x, b.x, acc[0][0]);
            acc[0][1] = fmaf(a.x, b.y, acc[0][1]);
            acc[0][2] = fmaf(a.x, b.z, acc[0][2]);
            acc[0][3] = fmaf(a.x, b.w, acc[0][3]);
            acc[1][0] = fmaf(a.y, b.x, acc[1][0]);
            acc[1][1] = fmaf(a.y, b.y, acc[1][1]);
            acc[1][2] = fmaf(a.y, b.z, acc[1][2]);
            acc[1][3] = fmaf(a.y, b.w, acc[1][3]);
            acc[2][0] = fmaf(a.z, b.x, acc[2][0]);
            acc[2][1] = fmaf(a.z, b.y, acc[2][1]);
            acc[2][2] = fmaf(a.z, b.z, acc[2][2]);
            acc[2][3] = fmaf(a.z, b.w, acc[2][3]);
            acc[3][0] = fmaf(a.w, b.x, acc[3][0]);
            acc[3][1] = fmaf(a.w, b.y, acc[3][1]);
            acc[3][2] = fmaf(a.w, b.z, acc[3][2]);
            acc[3][3] = fmaf(a.w, b.w, acc[3][3]);
        }
        __syncthreads();
    }

#pragma unroll
    for (int i = 0; i < 4; i++) {
        size_t off = (size_t)(bm + (ty << 2) + i) * N + bn + (tx << 2);
        float4 r;
        r.x = acc[i][0]; r.y = acc[i][1]; r.z = acc[i][2]; r.w = acc[i][3];
        if (BIAS) {
            const float* bb = bias + bn + (tx << 2);
            r.x += bb[0]; r.y += bb[1]; r.z += bb[2]; r.w += bb[3];
        }
        if (ACCUM) {
            float4 old = *(const float4*)(C + off);
            r.x += old.x; r.y += old.y; r.z += old.z; r.w += old.w;
        }
        *(float4*)(C + off) = r;
    }
}

// ------------------------------------------------------------------
// LSTM cell elementwise (Keras gate order i,f,g,o), bias folded here
// ------------------------------------------------------------------
__global__ void lstm_kernel(const float* __restrict__ z, const float* __restrict__ bias,
                            float* __restrict__ h, float* __restrict__ c)
{
    int idx = blockIdx.x * blockDim.x + threadIdx.x;
    if (idx >= BATCH * NUNITS) return;
    int b = idx >> 8, u = idx & 255;
    const float* zr = z + (size_t)b * GATES;
    float zi = zr[u]             + bias[u];
    float zf = zr[256 + u]       + bias[256 + u];
    float zg = zr[512 + u]       + bias[512 + u];
    float zo = zr[768 + u]       + bias[768 + u];
    float cn = sigmoidf_(zf) * c[idx] + sigmoidf_(zi) * tanhf(zg);
    float hn = sigmoidf_(zo) * tanhf(cn);
    c[idx] = cn;
    h[idx] = hn;
}

// ------------------------------------------------------------------
// attention: logits = h_enc @ W_enc + b_enc ; softmax ; z = attn @ W_enc^T
// also assembles dec input row [z | h_dec].  One block per batch row.
// ------------------------------------------------------------------
__global__ void attn_kernel(const float* __restrict__ Wenc, const float* __restrict__ benc,
                            const float* __restrict__ henc, const float* __restrict__ hdec,
                            float* __restrict__ decin)
{
    int b = blockIdx.x;
    int t = threadIdx.x;   // 0..255
    __shared__ float red[10][8];
    __shared__ float lg[10];

    float h = henc[b * NUNITS + t];
    float w[10];
#pragma unroll
    for (int s = 0; s < 10; s++) w[s] = Wenc[t * 10 + s];

    int lane = t & 31, warp = t >> 5;
#pragma unroll
    for (int s = 0; s < 10; s++) {
        float v = h * w[s];
        v += __shfl_down_sync(0xffffffffu, v, 16);
        v += __shfl_down_sync(0xffffffffu, v, 8);
        v += __shfl_down_sync(0xffffffffu, v, 4);
        v += __shfl_down_sync(0xffffffffu, v, 2);
        v += __shfl_down_sync(0xffffffffu, v, 1);
        if (lane == 0) red[s][warp] = v;
    }
    __syncthreads();
    if (t < 10) {
        float v = 0.f;
#pragma unroll
        for (int wg = 0; wg < 8; wg++) v += red[t][wg];
        lg[t] = v + benc[t];
    }
    __syncthreads();

    // each thread computes softmax locally over the 10 shared logits
    float mx = lg[0];
#pragma unroll
    for (int s = 1; s < 10; s++) mx = fmaxf(mx, lg[s]);
    float e[10], sum = 0.f;
#pragma unroll
    for (int s = 0; s < 10; s++) { e[s] = expf(lg[s] - mx); sum += e[s]; }
    float inv = 1.f / sum;
    float zv = 0.f;
#pragma unroll
    for (int s = 0; s < 10; s++) zv = fmaf(e[s] * inv, w[s], zv);

    decin[(size_t)b * DECK + t] = zv;
    decin[(size_t)b * DECK + NUNITS + t] = hdec[b * NUNITS + t];
}

// ------------------------------------------------------------------
extern "C" void kernel_launch(void* const* d_in, const int* in_sizes, int n_in,
                              void* d_out, int out_size)
{
    const float* x          = (const float*)d_in[0];
    const float* enc_kernel = (const float*)d_in[1];
    const float* enc_rec    = (const float*)d_in[2];
    const float* enc_bias   = (const float*)d_in[3];
    const float* dec_kernel = (const float*)d_in[4];
    const float* dec_rec    = (const float*)d_in[5];
    const float* dec_bias   = (const float*)d_in[6];
    const float* W_enc      = (const float*)d_in[7];
    const float* b_enc      = (const float*)d_in[8];
    const float* W_dec      = (const float*)d_in[9];
    const float* b_dec      = (const float*)d_in[10];
    float* canvas = (float*)d_out;

    float* base = nullptr;
    cudaGetSymbolAddress((void**)&base, g_scratch);
    float* Wenc  = base + OFF_WENC;
    float* Wdec  = base + OFF_WDEC;
    float* encin = base + OFF_ENCIN;
    float* decin = base + OFF_DECIN;
    float* xhat  = base + OFF_XHAT;
    float* zenc  = base + OFF_ZENC;
    float* zdec  = base + OFF_ZDEC;
    float* henc  = base + OFF_HENC;
    float* cenc  = base + OFF_CENC;
    float* hdec  = base + OFF_HDEC;
    float* cdec  = base + OFF_CDEC;

    setup_kernel<<<(ENCK * GATES + 255) / 256, 256>>>(
        enc_kernel, enc_rec, dec_kernel, dec_rec,
        Wenc, Wdec, henc, cenc, hdec, cdec, canvas);

    for (int step = 0; step < 10; ++step) {
        xhat_kernel<<<(BATCH * IMGD * IMGD + 255) / 256, 256>>>(x, canvas, xhat);
        gather_kernel<<<dim3(ENCK / 256, BATCH), 256>>>(xhat, hdec, henc, encin);
        sgemm64<false, false><<<dim3(GATES / 64, BATCH / 64), 256>>>(
            encin, Wenc, nullptr, zenc, BATCH, GATES, ENCK);
        lstm_kernel<<<(BATCH * NUNITS + 255) / 256, 256>>>(zenc, enc_bias, henc, cenc);
        attn_kernel<<<BATCH, 256>>>(W_enc, b_enc, henc, hdec, decin);
        sgemm64<false, false><<<dim3(GATES / 64, BATCH / 64), 256>>>(
            decin, Wdec, nullptr, zdec, BATCH, GATES, DECK);
        lstm_kernel<<<(BATCH * NUNITS + 255) / 256, 256>>>(zdec, dec_bias, hdec, cdec);
        sgemm64<true, true><<<dim3(IMGD * IMGD / 64, BATCH / 64), 256>>>(
            hdec, W_dec, b_dec, canvas, BATCH, IMGD * IMGD, NUNITS);
    }
}

// round 4
// speedup vs baseline: 1.1395x; 1.1387x over previous
#include <cuda_runtime.h>
#include <math.h>

#define BATCH 512
#define NUNITS 256
#define IMGD 64
#define PATCHD 9216      // 32*32*9
#define ENCK 9984        // 9216 + 256 + 256 (enc_kernel rows) + 256 (enc_rec rows)
#define GATES 1024
#define DECK 512
#define ESPLIT 4
#define DSPLIT 2

// ---- scratch partition (floats) ----
#define OFF_WENC   0u
#define SZ_WENC    (ENCK * GATES)                 // 10,223,616
#define OFF_WDEC   (OFF_WENC + SZ_WENC)
#define SZ_WDEC    (DECK * GATES)                 // 524,288
#define OFF_ENCIN  (OFF_WDEC + SZ_WDEC)
#define SZ_ENCIN   (BATCH * ENCK)                 // 5,111,808
#define OFF_DECIN  (OFF_ENCIN + SZ_ENCIN)
#define SZ_DECIN   (BATCH * DECK)                 // 262,144
#define OFF_XHAT   (OFF_DECIN + SZ_DECIN)
#define SZ_XHAT    (BATCH * IMGD * IMGD)          // 2,097,152
#define OFF_ZENC   (OFF_XHAT + SZ_XHAT)
#define SZ_Z       (BATCH * GATES)                // 524,288
#define OFF_ZDEC   (OFF_ZENC + ESPLIT * SZ_Z)
#define OFF_HENC   (OFF_ZDEC + DSPLIT * SZ_Z)
#define SZ_STATE   (BATCH * NUNITS)               // 131,072
#define OFF_CENC   (OFF_HENC + SZ_STATE)
#define OFF_HDEC   (OFF_CENC + SZ_STATE)
#define OFF_CDEC   (OFF_HDEC + SZ_STATE)
#define SCRATCH_TOTAL (OFF_CDEC + SZ_STATE)       // ~22M floats ~88 MB

__device__ float g_scratch[SCRATCH_TOTAL];

__device__ __forceinline__ float sigmoidf_(float x) { return 1.f / (1.f + expf(-x)); }

// ------------------------------------------------------------------
// setup: assemble combined weight matrices, zero states + canvas
// ------------------------------------------------------------------
__global__ void setup_kernel(const float* __restrict__ enc_k, const float* __restrict__ enc_r,
                             const float* __restrict__ dec_k, const float* __restrict__ dec_r,
                             float* __restrict__ Wenc, float* __restrict__ Wdec,
                             float* __restrict__ henc, float* __restrict__ cenc,
                             float* __restrict__ hdec, float* __restrict__ cdec,
                             float* __restrict__ canvas)
{
    const int NENC_K = 9728 * GATES;          // rows from enc_kernel
    const int NTOT   = ENCK * GATES;
    for (int i = blockIdx.x * blockDim.x + threadIdx.x; i < NTOT;
         i += gridDim.x * blockDim.x) {
        Wenc[i] = (i < NENC_K) ? enc_k[i] : enc_r[i - NENC_K];
        if (i < 256 * GATES)          Wdec[i] = dec_k[i];
        else if (i < 512 * GATES)     Wdec[i] = dec_r[i - 256 * GATES];
        if (i < BATCH * IMGD * IMGD)  canvas[i] = 0.f;
        if (i < BATCH * NUNITS) { henc[i] = 0.f; cenc[i] = 0.f; hdec[i] = 0.f; cdec[i] = 0.f; }
    }
}

// ------------------------------------------------------------------
// x_hat = x - sigmoid(canvas)
// ------------------------------------------------------------------
__global__ void xhat_kernel(const float* __restrict__ x, const float* __restrict__ canvas,
                            float* __restrict__ xhat)
{
    int i = blockIdx.x * blockDim.x + threadIdx.x;
    if (i < BATCH * IMGD * IMGD) xhat[i] = x[i] - sigmoidf_(canvas[i]);
}

// ------------------------------------------------------------------
// build enc_in row: [patches(9216) | h_dec | h_dec | h_enc]
// grid: (9984/256, BATCH)
// ------------------------------------------------------------------
__global__ void gather_kernel(const float* __restrict__ xhat, const float* __restrict__ hdec,
                              const float* __restrict__ henc, float* __restrict__ encin)
{
    int k = blockIdx.x * blockDim.x + threadIdx.x;   // 0..9983
    int b = blockIdx.y;
    float v;
    if (k < PATCHD) {
        int ip  = k / 288;           // 32*9
        int rem = k - ip * 288;
        int jp  = rem / 9;
        int t   = rem - jp * 9;
        int r = 2 * ip + t / 3;
        int c = 2 * jp + t % 3;
        v = (r < IMGD && c < IMGD) ? xhat[b * (IMGD * IMGD) + r * IMGD + c] : 0.f;
    } else if (k < PATCHD + NUNITS) {
        v = hdec[b * NUNITS + (k - PATCHD)];
    } else if (k < PATCHD + 2 * NUNITS) {
        v = hdec[b * NUNITS + (k - PATCHD - NUNITS)];
    } else {
        v = henc[b * NUNITS + (k - PATCHD - 2 * NUNITS)];
    }
    encin[(size_t)b * ENCK + k] = v;
}

// ------------------------------------------------------------------
// SGEMM: C[z][M,N] = A[M, K] @ B[K, N]  (K split across blockIdx.z)
// 64x64 tile, BK=16, 256 threads, 4x4 per thread, register prefetch.
// Requires M%64==0, N%64==0, (K/SPLIT)%16==0.
// ------------------------------------------------------------------
template<bool ACCUM, bool BIAS, int SPLIT>
__global__ void sgemm64(const float* __restrict__ A, const float* __restrict__ Bm,
                        const float* __restrict__ bias, float* __restrict__ C,
                        int M, int N, int K)
{
    __shared__ float As[16][64];
    __shared__ float Bs[16][64];
    const int tid = threadIdx.x;
    const int tx = tid & 15, ty = tid >> 4;
    const int bm = blockIdx.y * 64, bn = blockIdx.x * 64;
    const int arow = tid >> 2, acol = (tid & 3) << 2;
    const int brow = tid >> 4, bcol = (tid & 15) << 2;

    const int ks = K / SPLIT;
    const int z = (SPLIT > 1) ? blockIdx.z : 0;

    const float* Ap = A + (size_t)(bm + arow) * K + (size_t)z * ks + acol;
    const float* Bp = Bm + ((size_t)z * ks + brow) * N + bn + bcol;
    float* Cz = C + (size_t)z * M * N;

    float4 av = *(const float4*)Ap;
    float4 bv = *(const float4*)Bp;
    float acc[4][4] = {};

    for (int k0 = 16; k0 <= ks; k0 += 16) {
        As[acol + 0][arow] = av.x;
        As[acol + 1][arow] = av.y;
        As[acol + 2][arow] = av.z;
        As[acol + 3][arow] = av.w;
        *(float4*)&Bs[brow][bcol] = bv;
        __syncthreads();
        if (k0 < ks) {
            av = *(const float4*)(Ap + k0);
            bv = *(const float4*)(Bp + (size_t)k0 * N);
        }
#pragma unroll
        for (int kk = 0; kk < 16; kk++) {
            float4 a = *(const float4*)&As[kk][ty << 2];
            float4 b = *(const float4*)&Bs[kk][tx << 2];
            acc[0][0] = fmaf(a.x, b.x, acc[0][0]);
            acc[0][1] = fmaf(a.x, b.y, acc[0][1]);
            acc[0][2] = fmaf(a.x, b.z, acc[0][2]);
            acc[0][3] = fmaf(a.x, b.w, acc[0][3]);
            acc[1][0] = fmaf(a.y, b.x, acc[1][0]);
            acc[1][1] = fmaf(a.y, b.y, acc[1][1]);
            acc[1][2] = fmaf(a.y, b.z, acc[1][2]);
            acc[1][3] = fmaf(a.y, b.w, acc[1][3]);
            acc[2][0] = fmaf(a.z, b.x, acc[2][0]);
            acc[2][1] = fmaf(a.z, b.y, acc[2][1]);
            acc[2][2] = fmaf(a.z, b.z, acc[2][2]);
            acc[2][3] = fmaf(a.z, b.w, acc[2][3]);
            acc[3][0] = fmaf(a.w, b.x, acc[3][0]);
            acc[3][1] = fmaf(a.w, b.y, acc[3][1]);
            acc[3][2] = fmaf(a.w, b.z, acc[3][2]);
            acc[3][3] = fmaf(a.w, b.w, acc[3][3]);
        }
        __syncthreads();
    }

#pragma unroll
    for (int i = 0; i < 4; i++) {
        size_t off = (size_t)(bm + (ty << 2) + i) * N + bn + (tx << 2);
        float4 r;
        r.x = acc[i][0]; r.y = acc[i][1]; r.z = acc[i][2]; r.w = acc[i][3];
        if (BIAS) {
            const float* bb = bias + bn + (tx << 2);
            r.x += bb[0]; r.y += bb[1]; r.z += bb[2]; r.w += bb[3];
        }
        if (ACCUM) {
            float4 old = *(const float4*)(Cz + off);
            r.x += old.x; r.y += old.y; r.z += old.z; r.w += old.w;
        }
        *(float4*)(Cz + off) = r;
    }
}

// ------------------------------------------------------------------
// LSTM cell elementwise (Keras gate order i,f,g,o).
// Sums SPLIT partial GEMM results + bias (split-K reduction folded in).
// ------------------------------------------------------------------
template<int SPLIT>
__global__ void lstm_kernel(const float* __restrict__ z, const float* __restrict__ bias,
                            float* __restrict__ h, float* __restrict__ c)
{
    int idx = blockIdx.x * blockDim.x + threadIdx.x;
    if (idx >= BATCH * NUNITS) return;
    int b = idx >> 8, u = idx & 255;
    const float* zr = z + (size_t)b * GATES;
    float zi = bias[u];
    float zf = bias[256 + u];
    float zg = bias[512 + u];
    float zo = bias[768 + u];
#pragma unroll
    for (int s = 0; s < SPLIT; s++) {
        const float* zs = zr + (size_t)s * BATCH * GATES;
        zi += zs[u];
        zf += zs[256 + u];
        zg += zs[512 + u];
        zo += zs[768 + u];
    }
    float cn = sigmoidf_(zf) * c[idx] + sigmoidf_(zi) * tanhf(zg);
    float hn = sigmoidf_(zo) * tanhf(cn);
    c[idx] = cn;
    h[idx] = hn;
}

// ------------------------------------------------------------------
// attention: logits = h_enc @ W_enc + b_enc ; softmax ; z = attn @ W_enc^T
// also assembles dec input row [z | h_dec].  One block per batch row.
// ------------------------------------------------------------------
__global__ void attn_kernel(const float* __restrict__ Wenc, const float* __restrict__ benc,
                            const float* __restrict__ henc, const float* __restrict__ hdec,
                            float* __restrict__ decin)
{
    int b = blockIdx.x;
    int t = threadIdx.x;   // 0..255
    __shared__ float red[10][8];
    __shared__ float lg[10];

    float h = henc[b * NUNITS + t];
    float w[10];
#pragma unroll
    for (int s = 0; s < 10; s++) w[s] = Wenc[t * 10 + s];

    int lane = t & 31, warp = t >> 5;
#pragma unroll
    for (int s = 0; s < 10; s++) {
        float v = h * w[s];
        v += __shfl_down_sync(0xffffffffu, v, 16);
        v += __shfl_down_sync(0xffffffffu, v, 8);
        v += __shfl_down_sync(0xffffffffu, v, 4);
        v += __shfl_down_sync(0xffffffffu, v, 2);
        v += __shfl_down_sync(0xffffffffu, v, 1);
        if (lane == 0) red[s][warp] = v;
    }
    __syncthreads();
    if (t < 10) {
        float v = 0.f;
#pragma unroll
        for (int wg = 0; wg < 8; wg++) v += red[t][wg];
        lg[t] = v + benc[t];
    }
    __syncthreads();

    // each thread computes softmax locally over the 10 shared logits
    float mx = lg[0];
#pragma unroll
    for (int s = 1; s < 10; s++) mx = fmaxf(mx, lg[s]);
    float e[10], sum = 0.f;
#pragma unroll
    for (int s = 0; s < 10; s++) { e[s] = expf(lg[s] - mx); sum += e[s]; }
    float inv = 1.f / sum;
    float zv = 0.f;
#pragma unroll
    for (int s = 0; s < 10; s++) zv = fmaf(e[s] * inv, w[s], zv);

    decin[(size_t)b * DECK + t] = zv;
    decin[(size_t)b * DECK + NUNITS + t] = hdec[b * NUNITS + t];
}

// ------------------------------------------------------------------
extern "C" void kernel_launch(void* const* d_in, const int* in_sizes, int n_in,
                              void* d_out, int out_size)
{
    const float* x          = (const float*)d_in[0];
    const float* enc_kernel = (const float*)d_in[1];
    const float* enc_rec    = (const float*)d_in[2];
    const float* enc_bias   = (const float*)d_in[3];
    const float* dec_kernel = (const float*)d_in[4];
    const float* dec_rec    = (const float*)d_in[5];
    const float* dec_bias   = (const float*)d_in[6];
    const float* W_enc      = (const float*)d_in[7];
    const float* b_enc      = (const float*)d_in[8];
    const float* W_dec      = (const float*)d_in[9];
    const float* b_dec      = (const float*)d_in[10];
    float* canvas = (float*)d_out;

    float* base = nullptr;
    cudaGetSymbolAddress((void**)&base, g_scratch);
    float* Wenc  = base + OFF_WENC;
    float* Wdec  = base + OFF_WDEC;
    float* encin = base + OFF_ENCIN;
    float* decin = base + OFF_DECIN;
    float* xhat  = base + OFF_XHAT;
    float* zenc  = base + OFF_ZENC;
    float* zdec  = base + OFF_ZDEC;
    float* henc  = base + OFF_HENC;
    float* cenc  = base + OFF_CENC;
    float* hdec  = base + OFF_HDEC;
    float* cdec  = base + OFF_CDEC;

    setup_kernel<<<(ENCK * GATES + 255) / 256, 256>>>(
        enc_kernel, enc_rec, dec_kernel, dec_rec,
        Wenc, Wdec, henc, cenc, hdec, cdec, canvas);

    for (int step = 0; step < 10; ++step) {
        xhat_kernel<<<(BATCH * IMGD * IMGD + 255) / 256, 256>>>(x, canvas, xhat);
        gather_kernel<<<dim3(ENCK / 256, BATCH), 256>>>(xhat, hdec, henc, encin);
        sgemm64<false, false, ESPLIT><<<dim3(GATES / 64, BATCH / 64, ESPLIT), 256>>>(
            encin, Wenc, nullptr, zenc, BATCH, GATES, ENCK);
        lstm_kernel<ESPLIT><<<(BATCH * NUNITS + 255) / 256, 256>>>(zenc, enc_bias, henc, cenc);
        attn_kernel<<<BATCH, 256>>>(W_enc, b_enc, henc, hdec, decin);
        sgemm64<false, false, DSPLIT><<<dim3(GATES / 64, BATCH / 64, DSPLIT), 256>>>(
            decin, Wdec, nullptr, zdec, BATCH, GATES, DECK);
        lstm_kernel<DSPLIT><<<(BATCH * NUNITS + 255) / 256, 256>>>(zdec, dec_bias, hdec, cdec);
        sgemm64<true, true, 1><<<dim3(IMGD * IMGD / 64, BATCH / 64), 256>>>(
            hdec, W_dec, b_dec, canvas, BATCH, IMGD * IMGD, NUNITS);
    }
}